// round 9
// baseline (speedup 1.0000x reference)
#include <cuda_runtime.h>
#include <cuda_fp16.h>
#include <cstdint>

#define BATCH  4
#define SEQ    4096
#define HID    4096
#define OUTF   4096
#define RANK   64
#define NADAPT 8
#define KSPLIT 4

// ---------------------------------------------------------------------------
// Global scratch
// g_part: fp32 split-K partials [kp][b][s][r]
// g_bx:  fp16 [b][s][r]     g_at: fp16 [a][o][r]  (K-major, packed half2)
// ---------------------------------------------------------------------------
__device__ __align__(16) float    g_part[(size_t)KSPLIT * BATCH * SEQ * RANK];
__device__ __align__(16) uint32_t g_bx[BATCH * SEQ * RANK / 2];
__device__ __align__(16) uint32_t g_at[NADAPT * OUTF * RANK / 2];

#define SW128(b) ((b) ^ (((b) >> 3) & 0x70))

__device__ __forceinline__ uint32_t smem_u32(const void* p) {
    uint32_t a;
    asm("{ .reg .u64 t; cvta.to.shared.u64 t, %1; cvt.u32.u64 %0, t; }"
        : "=r"(a) : "l"(p));
    return a;
}

__device__ __forceinline__ void ldsm4(uint32_t r[4], uint32_t addr) {
    asm volatile("ldmatrix.sync.aligned.m8n8.x4.shared.b16 {%0,%1,%2,%3}, [%4];"
        : "=r"(r[0]), "=r"(r[1]), "=r"(r[2]), "=r"(r[3]) : "r"(addr));
}

__device__ __forceinline__ void mma16816(float c[4], const uint32_t a[4],
                                         uint32_t b0, uint32_t b1) {
    asm volatile(
        "mma.sync.aligned.m16n8k16.row.col.f32.f16.f16.f32 "
        "{%0,%1,%2,%3}, {%4,%5,%6,%7}, {%8,%9}, {%0,%1,%2,%3};"
        : "+f"(c[0]), "+f"(c[1]), "+f"(c[2]), "+f"(c[3])
        : "r"(a[0]), "r"(a[1]), "r"(a[2]), "r"(a[3]), "r"(b0), "r"(b1));
}

// pack two floats -> one f16x2 word (lo = a, hi = b)
__device__ __forceinline__ uint32_t packh2(float a, float b) {
    uint32_t r;
    asm("cvt.rn.f16x2.f32 %0, %1, %2;" : "=r"(r) : "f"(b), "f"(a));
    return r;
}

#define CPASYNC16(sm, gp) \
    asm volatile("cp.async.cg.shared.global [%0], [%1], 16;" \
                 :: "r"(sm), "l"(gp) : "memory")
#define CPASYNC_COMMIT() asm volatile("cp.async.commit_group;" ::: "memory")
#define CPASYNC_WAIT0()  asm volatile("cp.async.wait_group 0;" ::: "memory")

// ===========================================================================
// Stage 1 (merged): z < KSPLIT  -> split-K GEMM chunk
//                   z == KSPLIT -> prep_A (2 adapters per CTA)
// GEMM: CTA 128M x 64N, 16 chunks of 64, ping-pong smem, 1 barrier/chunk.
// Single-pass fp16. 8 warps = 4M x 2N, warp tile 32x32. grid (32,4,5).
// ===========================================================================
#define S1_X   0
#define S1_B   16384
#define S1_BUF 24576
#define S1_SMEM (2 * S1_BUF)
#define S1_KC   (HID / KSPLIT / 64)     // 16 chunks

__global__ __launch_bounds__(256, 3) void lora_s1(
    const float* __restrict__ x, const int* __restrict__ ids,
    const float* __restrict__ Bw, const float* __restrict__ A)
{
    extern __shared__ __align__(128) uint8_t sm1[];
    const int tid = threadIdx.x, lane = tid & 31, wid = tid >> 5;

    // ---------------- prep_A plane ----------------
    if (blockIdx.z == KSPLIT) {
        float (*As)[132] = (float (*)[132])sm1;      // 64 x 132 fp32 = 33 KB
        const int o0 = blockIdx.x * 128;
        #pragma unroll 1
        for (int ay = 0; ay < 2; ++ay) {
            const int a = blockIdx.y * 2 + ay;
            #pragma unroll
            for (int i = 0; i < 8; ++i) {
                int idx = tid + i * 256;
                int r = idx >> 5, og = idx & 31;
                *(float4*)&As[r][og * 4] = *(const float4*)(
                    A + (size_t)a * RANK * OUTF + (size_t)r * OUTF + o0 + og * 4);
            }
            __syncthreads();

            const int o = tid >> 1, r0 = (tid & 1) * 32;
            __align__(16) uint32_t hb[16];
            #pragma unroll
            for (int j = 0; j < 16; ++j)
                hb[j] = packh2(As[r0 + 2 * j][o], As[r0 + 2 * j + 1][o]);

            size_t base = ((size_t)(a * OUTF + o0 + o) * RANK + r0) / 2;
            #pragma unroll
            for (int q = 0; q < 4; ++q)
                *(uint4*)(g_at + base + q * 4) = *(uint4*)(hb + q * 4);
            __syncthreads();
        }
        return;
    }

    // ---------------- split-K GEMM plane ----------------
    const int wm = wid & 3, wn = wid >> 2;           // 4M x 2N warps
    const int b = blockIdx.y;
    const int kp = blockIdx.z;
    const int a = ids[b];
    const int m0 = blockIdx.x * 128;
    const int k0 = kp * (HID / KSPLIT);

    const uint32_t smb = smem_u32(sm1);
    const int lr = lane & 15;
    const uint32_t lcol = (uint32_t)(lane >> 4) * 16;

    uint32_t aterm[2], axor[2], bterm[2], bxor[2];
    #pragma unroll
    for (int t = 0; t < 2; ++t) {
        int ar = wm * 32 + t * 16 + lr;
        aterm[t] = (uint32_t)ar * 128; axor[t] = (uint32_t)(ar & 7) << 4;
        int br = wn * 32 + t * 16 + lr;
        bterm[t] = (uint32_t)br * 128; bxor[t] = (uint32_t)(br & 7) << 4;
    }

    float acc[2][4][4];
    #pragma unroll
    for (int i = 0; i < 2; ++i)
        #pragma unroll
        for (int j = 0; j < 4; ++j)
            #pragma unroll
            for (int k = 0; k < 4; ++k) acc[i][j][k] = 0.f;

    const int xkg = tid & 15;                 // k-group within 64 (4 k each)
    const int bih = tid & 31;                 // h-pair index (conflict-free STS)
    const int brg0 = tid >> 5;                // rank groups brg0 and brg0+8

    float4 xv[8], bv0[2], bv1[2];

    // ---- prefetch chunk 0 ----
    #pragma unroll
    for (int i = 0; i < 8; ++i) {
        int m = (tid + i * 256) >> 4;
        xv[i] = *(const float4*)(x + (size_t)(b * SEQ + m0 + m) * HID + k0 + xkg * 4);
    }
    #pragma unroll
    for (int i = 0; i < 2; ++i) {
        const float* p = Bw + (size_t)(k0 + 2 * bih) * (NADAPT * RANK) + a * RANK
                       + (brg0 + i * 8) * 4;
        bv0[i] = *(const float4*)p;
        bv1[i] = *(const float4*)(p + NADAPT * RANK);
    }

    // ---- convert chunk 0 into buf 0 ----
    #pragma unroll
    for (int i = 0; i < 8; ++i) {
        int m = (tid + i * 256) >> 4;
        uint32_t s0 = SW128((uint32_t)m * 128 + xkg * 8);
        *(uint2*)(sm1 + S1_X + s0) =
            make_uint2(packh2(xv[i].x, xv[i].y), packh2(xv[i].z, xv[i].w));
    }
    #pragma unroll
    for (int i = 0; i < 2; ++i) {
        const float* f0 = &bv0[i].x;
        const float* f1 = &bv1[i].x;
        #pragma unroll
        for (int j = 0; j < 4; ++j) {
            uint32_t so = SW128((uint32_t)((brg0 + i * 8) * 4 + j) * 128 + bih * 4);
            *(uint32_t*)(sm1 + S1_B + so) = packh2(f0[j], f1[j]);
        }
    }
    __syncthreads();

    for (int it = 0; it < S1_KC; ++it) {
        const uint32_t pb = (uint32_t)(it & 1) * S1_BUF;

        if (it + 1 < S1_KC) {
            int kc = k0 + (it + 1) * 64;
            #pragma unroll
            for (int i = 0; i < 8; ++i) {
                int m = (tid + i * 256) >> 4;
                xv[i] = *(const float4*)(x + (size_t)(b * SEQ + m0 + m) * HID + kc + xkg * 4);
            }
            #pragma unroll
            for (int i = 0; i < 2; ++i) {
                const float* p = Bw + (size_t)(kc + 2 * bih) * (NADAPT * RANK) + a * RANK
                               + (brg0 + i * 8) * 4;
                bv0[i] = *(const float4*)p;
                bv1[i] = *(const float4*)(p + NADAPT * RANK);
            }
        }

        #pragma unroll
        for (int ks = 0; ks < 4; ++ks) {
            uint32_t cb = lcol + (uint32_t)ks * 32;
            uint32_t a0[4], a1[4], b0[4], b1[4];
            ldsm4(a0, smb + S1_X + pb + aterm[0] + (cb ^ axor[0]));
            ldsm4(a1, smb + S1_X + pb + aterm[1] + (cb ^ axor[1]));
            ldsm4(b0, smb + S1_B + pb + bterm[0] + (cb ^ bxor[0]));
            ldsm4(b1, smb + S1_B + pb + bterm[1] + (cb ^ bxor[1]));

            mma16816(acc[0][0], a0, b0[0], b0[2]);
            mma16816(acc[0][1], a0, b0[1], b0[3]);
            mma16816(acc[0][2], a0, b1[0], b1[2]);
            mma16816(acc[0][3], a0, b1[1], b1[3]);
            mma16816(acc[1][0], a1, b0[0], b0[2]);
            mma16816(acc[1][1], a1, b0[1], b0[3]);
            mma16816(acc[1][2], a1, b1[0], b1[2]);
            mma16816(acc[1][3], a1, b1[1], b1[3]);
        }

        if (it + 1 < S1_KC) {
            const uint32_t qb = pb ^ S1_BUF;
            #pragma unroll
            for (int i = 0; i < 8; ++i) {
                int m = (tid + i * 256) >> 4;
                uint32_t s0 = SW128((uint32_t)m * 128 + xkg * 8);
                *(uint2*)(sm1 + S1_X + qb + s0) =
                    make_uint2(packh2(xv[i].x, xv[i].y), packh2(xv[i].z, xv[i].w));
            }
            #pragma unroll
            for (int i = 0; i < 2; ++i) {
                const float* f0 = &bv0[i].x;
                const float* f1 = &bv1[i].x;
                #pragma unroll
                for (int j = 0; j < 4; ++j) {
                    uint32_t so = SW128((uint32_t)((brg0 + i * 8) * 4 + j) * 128 + bih * 4);
                    *(uint32_t*)(sm1 + S1_B + qb + so) = packh2(f0[j], f1[j]);
                }
            }
        }
        __syncthreads();
    }

    // ---- epilogue: raw fp32 partial sums, float2 per c-pair ----
    float* pp = g_part + (size_t)(kp * BATCH + b) * SEQ * RANK;
    #pragma unroll
    for (int mt = 0; mt < 2; ++mt)
        #pragma unroll
        for (int nt = 0; nt < 4; ++nt)
            #pragma unroll
            for (int rh = 0; rh < 2; ++rh) {
                int s = m0 + wm * 32 + mt * 16 + rh * 8 + (lane >> 2);
                int r = wn * 32 + nt * 8 + 2 * (lane & 3);
                float2 v = { acc[mt][nt][2 * rh], acc[mt][nt][2 * rh + 1] };
                *(float2*)(pp + (size_t)s * RANK + r) = v;
            }
}

// ===========================================================================
// bx_reduce: sum 4 split-K partials -> fp16 g_bx
// grid 1024 x 256 thr, one float4 (4 elems) per thread
// ===========================================================================
__global__ __launch_bounds__(256) void lora_bx_reduce() {
    const size_t gid = (size_t)blockIdx.x * 256 + threadIdx.x;   // float4 units
    const size_t stride = (size_t)BATCH * SEQ * RANK / 4;
    const float4* p = (const float4*)g_part;
    float4 v0 = p[gid];
    float4 v1 = p[gid + stride];
    float4 v2 = p[gid + 2 * stride];
    float4 v3 = p[gid + 3 * stride];
    float4 s;
    s.x = (v0.x + v1.x) + (v2.x + v3.x);
    s.y = (v0.y + v1.y) + (v2.y + v3.y);
    s.z = (v0.z + v1.z) + (v2.z + v3.z);
    s.w = (v0.w + v1.w) + (v2.w + v3.w);
    ((uint2*)g_bx)[gid] = make_uint2(packh2(s.x, s.y), packh2(s.z, s.w));
}

// ===========================================================================
// Stage 2: out[b][s][o] = Bx[b][s][:] @ At[a][o][:] / 64
// CTA 128M x 64N, K=64 one-shot, fp16, cp.async fill.
// Epilogue stages D through smem (stride-68 rows) for coalesced STG.128.
// 8 warps = 4M x 2N, warp tile 32x32. grid (64, 32, 4). smem 34816 B.
// ===========================================================================
#define S2_X 0
#define S2_A 16384
#define S2_DS_STRIDE 68
#define S2_SMEM (128 * S2_DS_STRIDE * 4)    // 34816 >= 24576 operands

__global__ __launch_bounds__(256, 3) void lora_s2(
    const int* __restrict__ ids, float* __restrict__ out)
{
    extern __shared__ __align__(128) uint8_t sm2[];
    const int tid = threadIdx.x, lane = tid & 31, wid = tid >> 5;
    const int wm = wid & 3, wn = wid >> 2;           // 4M x 2N warps
    const int o0 = blockIdx.x * 64, m0 = blockIdx.y * 128, b = blockIdx.z;
    const int a = ids[b];

    const uint32_t smb = smem_u32(sm2);

    // ---- cp.async smem fill (rows are 128B: 64 fp16 K-major) ----
    #pragma unroll
    for (int i = 0; i < 4; ++i) {
        int idx = tid + i * 256;             // 1024 uint4 slots
        int row = idx >> 3, rg = idx & 7;
        uint32_t so = SW128((uint32_t)row * 128 + rg * 16);
        size_t bx = (size_t)(b * SEQ + m0 + row) * 8 + rg;
        CPASYNC16(smb + S2_X + so, (const uint4*)g_bx + bx);
    }
    #pragma unroll
    for (int i = 0; i < 2; ++i) {
        int idx = tid + i * 256;             // 512 uint4 slots
        int row = idx >> 3, rg = idx & 7;
        uint32_t so = SW128((uint32_t)row * 128 + rg * 16);
        size_t at = (size_t)(a * OUTF + o0 + row) * 8 + rg;
        CPASYNC16(smb + S2_A + so, (const uint4*)g_at + at);
    }
    CPASYNC_COMMIT();
    CPASYNC_WAIT0();
    __syncthreads();

    const int lr = lane & 15;
    const uint32_t lcol = (uint32_t)(lane >> 4) * 16;

    uint32_t aterm[2], axor[2], bterm[2], bxor[2];
    #pragma unroll
    for (int t = 0; t < 2; ++t) {
        int ar = wm * 32 + t * 16 + lr;
        aterm[t] = (uint32_t)ar * 128; axor[t] = (uint32_t)(ar & 7) << 4;
        int br = wn * 32 + t * 16 + lr;
        bterm[t] = (uint32_t)br * 128; bxor[t] = (uint32_t)(br & 7) << 4;
    }

    float acc[2][4][4];
    #pragma unroll
    for (int i = 0; i < 2; ++i)
        #pragma unroll
        for (int j = 0; j < 4; ++j)
            #pragma unroll
            for (int k = 0; k < 4; ++k) acc[i][j][k] = 0.f;

    #pragma unroll
    for (int ks = 0; ks < 4; ++ks) {
        uint32_t cb = lcol + (uint32_t)ks * 32;
        uint32_t a0[4], a1[4], b0[4], b1[4];
        ldsm4(a0, smb + S2_X + aterm[0] + (cb ^ axor[0]));
        ldsm4(a1, smb + S2_X + aterm[1] + (cb ^ axor[1]));
        ldsm4(b0, smb + S2_A + bterm[0] + (cb ^ bxor[0]));
        ldsm4(b1, smb + S2_A + bterm[1] + (cb ^ bxor[1]));

        mma16816(acc[0][0], a0, b0[0], b0[2]);
        mma16816(acc[0][1], a0, b0[1], b0[3]);
        mma16816(acc[0][2], a0, b1[0], b1[2]);
        mma16816(acc[0][3], a0, b1[1], b1[3]);
        mma16816(acc[1][0], a1, b0[0], b0[2]);
        mma16816(acc[1][1], a1, b0[1], b0[3]);
        mma16816(acc[1][2], a1, b1[0], b1[2]);
        mma16816(acc[1][3], a1, b1[1], b1[3]);
    }
    __syncthreads();          // all ldsm reads complete; reuse smem for D

    // ---- stage scaled D into smem (stride-68 fp32 rows) ----
    const float sc = 1.0f / (float)RANK;
    float* ds = (float*)sm2;
    #pragma unroll
    for (int mt = 0; mt < 2; ++mt)
        #pragma unroll
        for (int nt = 0; nt < 4; ++nt) {
            int row = wm * 32 + mt * 16 + (lane >> 2);
            int col = wn * 32 + nt * 8 + 2 * (lane & 3);
            float2 v0 = { acc[mt][nt][0] * sc, acc[mt][nt][1] * sc };
            float2 v1 = { acc[mt][nt][2] * sc, acc[mt][nt][3] * sc };
            *(float2*)(ds + (size_t)row * S2_DS_STRIDE + col) = v0;
            *(float2*)(ds + (size_t)(row + 8) * S2_DS_STRIDE + col) = v1;
        }
    __syncthreads();

    // ---- coalesced write-out: STG.128, contiguous 64B per 16 lanes ----
    #pragma unroll
    for (int i = 0; i < 8; ++i) {
        int idx = tid + i * 256;             // 2048 float4 slots
        int row = idx >> 4, cg = idx & 15;
        float4 v = *(float4*)(ds + (size_t)row * S2_DS_STRIDE + cg * 4);
        *(float4*)(out + (size_t)(b * SEQ + m0 + row) * OUTF + o0 + cg * 4) = v;
    }
}

// ===========================================================================
extern "C" void kernel_launch(void* const* d_in, const int* in_sizes, int n_in,
                              void* d_out, int out_size)
{
    const float* x   = (const float*)d_in[0];
    const int*   ids = (const int*)  d_in[1];
    const float* A   = (const float*)d_in[2];
    const float* Bw  = (const float*)d_in[3];
    float* out = (float*)d_out;

    cudaFuncSetAttribute(lora_s1, cudaFuncAttributeMaxDynamicSharedMemorySize, S1_SMEM);
    cudaFuncSetAttribute(lora_s2, cudaFuncAttributeMaxDynamicSharedMemorySize, S2_SMEM);

    // z = 0..3: split-K GEMM planes; z = 4: prep_A (runs concurrently)
    lora_s1<<<dim3(SEQ / 128, BATCH, KSPLIT + 1), 256, S1_SMEM>>>(x, ids, Bw, A);
    lora_bx_reduce<<<BATCH * SEQ * RANK / 4 / 256, 256>>>();
    lora_s2<<<dim3(OUTF / 64, SEQ / 128, BATCH), 256, S2_SMEM>>>(ids, out);
}

// round 10
// speedup vs baseline: 1.4270x; 1.4270x over previous
#include <cuda_runtime.h>
#include <cuda_fp16.h>
#include <cstdint>

#define BATCH  4
#define SEQ    4096
#define HID    4096
#define OUTF   4096
#define RANK   64
#define NADAPT 8
#define KSPLIT 4

// ---------------------------------------------------------------------------
// Global scratch
// g_part: fp32 split-K partials [kp][b][s][r]
// g_bx:  fp16 [b][s][r]     g_at: fp16 [a][o][r]  (K-major, packed half2)
// ---------------------------------------------------------------------------
__device__ __align__(16) float    g_part[(size_t)KSPLIT * BATCH * SEQ * RANK];
__device__ __align__(16) uint32_t g_bx[BATCH * SEQ * RANK / 2];
__device__ __align__(16) uint32_t g_at[NADAPT * OUTF * RANK / 2];

#define SW128(b) ((b) ^ (((b) >> 3) & 0x70))

__device__ __forceinline__ uint32_t smem_u32(const void* p) {
    uint32_t a;
    asm("{ .reg .u64 t; cvta.to.shared.u64 t, %1; cvt.u32.u64 %0, t; }"
        : "=r"(a) : "l"(p));
    return a;
}

__device__ __forceinline__ void ldsm4(uint32_t r[4], uint32_t addr) {
    asm volatile("ldmatrix.sync.aligned.m8n8.x4.shared.b16 {%0,%1,%2,%3}, [%4];"
        : "=r"(r[0]), "=r"(r[1]), "=r"(r[2]), "=r"(r[3]) : "r"(addr));
}

__device__ __forceinline__ void mma16816(float c[4], const uint32_t a[4],
                                         uint32_t b0, uint32_t b1) {
    asm volatile(
        "mma.sync.aligned.m16n8k16.row.col.f32.f16.f16.f32 "
        "{%0,%1,%2,%3}, {%4,%5,%6,%7}, {%8,%9}, {%0,%1,%2,%3};"
        : "+f"(c[0]), "+f"(c[1]), "+f"(c[2]), "+f"(c[3])
        : "r"(a[0]), "r"(a[1]), "r"(a[2]), "r"(a[3]), "r"(b0), "r"(b1));
}

// pack two floats -> one f16x2 word (lo = a, hi = b)
__device__ __forceinline__ uint32_t packh2(float a, float b) {
    uint32_t r;
    asm("cvt.rn.f16x2.f32 %0, %1, %2;" : "=r"(r) : "f"(b), "f"(a));
    return r;
}

#define CPASYNC16(sm, gp) \
    asm volatile("cp.async.cg.shared.global [%0], [%1], 16;" \
                 :: "r"(sm), "l"(gp) : "memory")
#define CPASYNC_COMMIT() asm volatile("cp.async.commit_group;" ::: "memory")
#define CPASYNC_WAIT0()  asm volatile("cp.async.wait_group 0;" ::: "memory")

// ===========================================================================
// prep_A: A[a][r][o] fp32 -> g_at [a][o][r] fp16 (K-major)
// grid (32 o-tiles, 8 adapters), 256 thr
// ===========================================================================
__global__ __launch_bounds__(256) void lora_prep_a(const float* __restrict__ A) {
    __shared__ float As[64][132];
    const int a  = blockIdx.y;
    const int o0 = blockIdx.x * 128;
    const int tid = threadIdx.x;

    #pragma unroll
    for (int i = 0; i < 8; ++i) {
        int idx = tid + i * 256;
        int r = idx >> 5, og = idx & 31;
        *(float4*)&As[r][og * 4] =
            *(const float4*)(A + (size_t)a * RANK * OUTF + (size_t)r * OUTF + o0 + og * 4);
    }
    __syncthreads();

    const int o = tid >> 1, r0 = (tid & 1) * 32;
    __align__(16) uint32_t hb[16];
    #pragma unroll
    for (int j = 0; j < 16; ++j)
        hb[j] = packh2(As[r0 + 2 * j][o], As[r0 + 2 * j + 1][o]);

    size_t base = ((size_t)(a * OUTF + o0 + o) * RANK + r0) / 2;   // uint32 units
    #pragma unroll
    for (int q = 0; q < 4; ++q)
        *(uint4*)(g_at + base + q * 4) = *(uint4*)(hb + q * 4);
}

// ===========================================================================
// Stage 1: partial[kp][b][s][r] = x[b][s][k0:k0+1024] @ B[k0:k0+1024][a][r]
// CTA 128M x 64N, split-K=4, 16 chunks of 64, ping-pong smem, 1 barrier/chunk.
// Single-pass fp16. 8 warps = 4M x 2N, warp tile 32x32. grid (32,4,4), 2/SM.
// (minblocks MUST stay 2: reg cap 128; minblocks 3 caps at 85 -> spills, R9.)
// ===========================================================================
#define S1_X   0
#define S1_B   16384
#define S1_BUF 24576
#define S1_SMEM (2 * S1_BUF)
#define S1_KC   (HID / KSPLIT / 64)     // 16 chunks

__global__ __launch_bounds__(256, 2) void lora_s1(
    const float* __restrict__ x, const int* __restrict__ ids,
    const float* __restrict__ Bw)
{
    extern __shared__ __align__(128) uint8_t sm1[];
    const int tid = threadIdx.x, lane = tid & 31, wid = tid >> 5;
    const int wm = wid & 3, wn = wid >> 2;           // 4M x 2N warps
    const int b = blockIdx.y;
    const int kp = blockIdx.z;
    const int a = ids[b];
    const int m0 = blockIdx.x * 128;
    const int k0 = kp * (HID / KSPLIT);

    const uint32_t smb = smem_u32(sm1);
    const int lr = lane & 15;
    const uint32_t lcol = (uint32_t)(lane >> 4) * 16;

    uint32_t aterm[2], axor[2], bterm[2], bxor[2];
    #pragma unroll
    for (int t = 0; t < 2; ++t) {
        int ar = wm * 32 + t * 16 + lr;
        aterm[t] = (uint32_t)ar * 128; axor[t] = (uint32_t)(ar & 7) << 4;
        int br = wn * 32 + t * 16 + lr;
        bterm[t] = (uint32_t)br * 128; bxor[t] = (uint32_t)(br & 7) << 4;
    }

    float acc[2][4][4];
    #pragma unroll
    for (int i = 0; i < 2; ++i)
        #pragma unroll
        for (int j = 0; j < 4; ++j)
            #pragma unroll
            for (int k = 0; k < 4; ++k) acc[i][j][k] = 0.f;

    // per-thread load/convert coordinates
    const int xkg = tid & 15;                 // k-group within 64 (4 k each)
    const int bih = tid & 31;                 // h-pair index (conflict-free STS)
    const int brg0 = tid >> 5;                // rank groups brg0 and brg0+8

    float4 xv[8], bv0[2], bv1[2];

    // ---- prefetch chunk 0 ----
    #pragma unroll
    for (int i = 0; i < 8; ++i) {
        int m = (tid + i * 256) >> 4;
        xv[i] = *(const float4*)(x + (size_t)(b * SEQ + m0 + m) * HID + k0 + xkg * 4);
    }
    #pragma unroll
    for (int i = 0; i < 2; ++i) {
        const float* p = Bw + (size_t)(k0 + 2 * bih) * (NADAPT * RANK) + a * RANK
                       + (brg0 + i * 8) * 4;
        bv0[i] = *(const float4*)p;
        bv1[i] = *(const float4*)(p + NADAPT * RANK);
    }

    // ---- convert chunk 0 into buf 0 ----
    #pragma unroll
    for (int i = 0; i < 8; ++i) {
        int m = (tid + i * 256) >> 4;
        uint32_t s0 = SW128((uint32_t)m * 128 + xkg * 8);
        *(uint2*)(sm1 + S1_X + s0) =
            make_uint2(packh2(xv[i].x, xv[i].y), packh2(xv[i].z, xv[i].w));
    }
    #pragma unroll
    for (int i = 0; i < 2; ++i) {
        const float* f0 = &bv0[i].x;
        const float* f1 = &bv1[i].x;
        #pragma unroll
        for (int j = 0; j < 4; ++j) {
            uint32_t so = SW128((uint32_t)((brg0 + i * 8) * 4 + j) * 128 + bih * 4);
            *(uint32_t*)(sm1 + S1_B + so) = packh2(f0[j], f1[j]);
        }
    }
    __syncthreads();

    for (int it = 0; it < S1_KC; ++it) {
        const uint32_t pb = (uint32_t)(it & 1) * S1_BUF;

        // ---- prefetch chunk it+1 (LDG latency hides under MMA) ----
        if (it + 1 < S1_KC) {
            int kc = k0 + (it + 1) * 64;
            #pragma unroll
            for (int i = 0; i < 8; ++i) {
                int m = (tid + i * 256) >> 4;
                xv[i] = *(const float4*)(x + (size_t)(b * SEQ + m0 + m) * HID + kc + xkg * 4);
            }
            #pragma unroll
            for (int i = 0; i < 2; ++i) {
                const float* p = Bw + (size_t)(kc + 2 * bih) * (NADAPT * RANK) + a * RANK
                               + (brg0 + i * 8) * 4;
                bv0[i] = *(const float4*)p;
                bv1[i] = *(const float4*)(p + NADAPT * RANK);
            }
        }

        // ---- MMA over buf pb ----
        #pragma unroll
        for (int ks = 0; ks < 4; ++ks) {
            uint32_t cb = lcol + (uint32_t)ks * 32;
            uint32_t a0[4], a1[4], b0[4], b1[4];
            ldsm4(a0, smb + S1_X + pb + aterm[0] + (cb ^ axor[0]));
            ldsm4(a1, smb + S1_X + pb + aterm[1] + (cb ^ axor[1]));
            ldsm4(b0, smb + S1_B + pb + bterm[0] + (cb ^ bxor[0]));
            ldsm4(b1, smb + S1_B + pb + bterm[1] + (cb ^ bxor[1]));

            mma16816(acc[0][0], a0, b0[0], b0[2]);
            mma16816(acc[0][1], a0, b0[1], b0[3]);
            mma16816(acc[0][2], a0, b1[0], b1[2]);
            mma16816(acc[0][3], a0, b1[1], b1[3]);
            mma16816(acc[1][0], a1, b0[0], b0[2]);
            mma16816(acc[1][1], a1, b0[1], b0[3]);
            mma16816(acc[1][2], a1, b1[0], b1[2]);
            mma16816(acc[1][3], a1, b1[1], b1[3]);
        }

        // ---- convert chunk it+1 into the other buffer ----
        if (it + 1 < S1_KC) {
            const uint32_t qb = pb ^ S1_BUF;
            #pragma unroll
            for (int i = 0; i < 8; ++i) {
                int m = (tid + i * 256) >> 4;
                uint32_t s0 = SW128((uint32_t)m * 128 + xkg * 8);
                *(uint2*)(sm1 + S1_X + qb + s0) =
                    make_uint2(packh2(xv[i].x, xv[i].y), packh2(xv[i].z, xv[i].w));
            }
            #pragma unroll
            for (int i = 0; i < 2; ++i) {
                const float* f0 = &bv0[i].x;
                const float* f1 = &bv1[i].x;
                #pragma unroll
                for (int j = 0; j < 4; ++j) {
                    uint32_t so = SW128((uint32_t)((brg0 + i * 8) * 4 + j) * 128 + bih * 4);
                    *(uint32_t*)(sm1 + S1_B + qb + so) = packh2(f0[j], f1[j]);
                }
            }
        }
        __syncthreads();
    }

    // ---- epilogue: raw fp32 partial sums, float2 per c-pair ----
    float* pp = g_part + (size_t)(kp * BATCH + b) * SEQ * RANK;
    #pragma unroll
    for (int mt = 0; mt < 2; ++mt)
        #pragma unroll
        for (int nt = 0; nt < 4; ++nt)
            #pragma unroll
            for (int rh = 0; rh < 2; ++rh) {
                int s = m0 + wm * 32 + mt * 16 + rh * 8 + (lane >> 2);
                int r = wn * 32 + nt * 8 + 2 * (lane & 3);
                float2 v = { acc[mt][nt][2 * rh], acc[mt][nt][2 * rh + 1] };
                *(float2*)(pp + (size_t)s * RANK + r) = v;
            }
}

// ===========================================================================
// bx_reduce: sum 4 split-K partials -> fp16 g_bx
// grid 1024 x 256 thr, one float4 (4 elems) per thread
// ===========================================================================
__global__ __launch_bounds__(256) void lora_bx_reduce() {
    const size_t gid = (size_t)blockIdx.x * 256 + threadIdx.x;   // float4 units
    const size_t stride = (size_t)BATCH * SEQ * RANK / 4;
    const float4* p = (const float4*)g_part;
    float4 v0 = p[gid];
    float4 v1 = p[gid + stride];
    float4 v2 = p[gid + 2 * stride];
    float4 v3 = p[gid + 3 * stride];
    float4 s;
    s.x = (v0.x + v1.x) + (v2.x + v3.x);
    s.y = (v0.y + v1.y) + (v2.y + v3.y);
    s.z = (v0.z + v1.z) + (v2.z + v3.z);
    s.w = (v0.w + v1.w) + (v2.w + v3.w);
    ((uint2*)g_bx)[gid] = make_uint2(packh2(s.x, s.y), packh2(s.z, s.w));
}

// ===========================================================================
// Stage 2: out[b][s][o] = Bx[b][s][:] @ At[a][o][:] / 64
// CTA 128M x 64N, K=64 one-shot, fp16, cp.async fill.
// Epilogue stages D through smem (stride-68 rows) for coalesced STG.128.
// 8 warps = 4M x 2N, warp tile 32x32. grid (64, 32, 4). smem 34816 B.
// ===========================================================================
#define S2_X 0
#define S2_A 16384
#define S2_DS_STRIDE 68
#define S2_SMEM (128 * S2_DS_STRIDE * 4)    // 34816 >= 24576 operands

__global__ __launch_bounds__(256, 3) void lora_s2(
    const int* __restrict__ ids, float* __restrict__ out)
{
    extern __shared__ __align__(128) uint8_t sm2[];
    const int tid = threadIdx.x, lane = tid & 31, wid = tid >> 5;
    const int wm = wid & 3, wn = wid >> 2;           // 4M x 2N warps
    const int o0 = blockIdx.x * 64, m0 = blockIdx.y * 128, b = blockIdx.z;
    const int a = ids[b];

    const uint32_t smb = smem_u32(sm2);

    // ---- cp.async smem fill (rows are 128B: 64 fp16 K-major) ----
    #pragma unroll
    for (int i = 0; i < 4; ++i) {
        int idx = tid + i * 256;             // 1024 uint4 slots
        int row = idx >> 3, rg = idx & 7;
        uint32_t so = SW128((uint32_t)row * 128 + rg * 16);
        size_t bx = (size_t)(b * SEQ + m0 + row) * 8 + rg;
        CPASYNC16(smb + S2_X + so, (const uint4*)g_bx + bx);
    }
    #pragma unroll
    for (int i = 0; i < 2; ++i) {
        int idx = tid + i * 256;             // 512 uint4 slots
        int row = idx >> 3, rg = idx & 7;
        uint32_t so = SW128((uint32_t)row * 128 + rg * 16);
        size_t at = (size_t)(a * OUTF + o0 + row) * 8 + rg;
        CPASYNC16(smb + S2_A + so, (const uint4*)g_at + at);
    }
    CPASYNC_COMMIT();
    CPASYNC_WAIT0();
    __syncthreads();

    const int lr = lane & 15;
    const uint32_t lcol = (uint32_t)(lane >> 4) * 16;

    uint32_t aterm[2], axor[2], bterm[2], bxor[2];
    #pragma unroll
    for (int t = 0; t < 2; ++t) {
        int ar = wm * 32 + t * 16 + lr;
        aterm[t] = (uint32_t)ar * 128; axor[t] = (uint32_t)(ar & 7) << 4;
        int br = wn * 32 + t * 16 + lr;
        bterm[t] = (uint32_t)br * 128; bxor[t] = (uint32_t)(br & 7) << 4;
    }

    float acc[2][4][4];
    #pragma unroll
    for (int i = 0; i < 2; ++i)
        #pragma unroll
        for (int j = 0; j < 4; ++j)
            #pragma unroll
            for (int k = 0; k < 4; ++k) acc[i][j][k] = 0.f;

    #pragma unroll
    for (int ks = 0; ks < 4; ++ks) {
        uint32_t cb = lcol + (uint32_t)ks * 32;
        uint32_t a0[4], a1[4], b0[4], b1[4];
        ldsm4(a0, smb + S2_X + aterm[0] + (cb ^ axor[0]));
        ldsm4(a1, smb + S2_X + aterm[1] + (cb ^ axor[1]));
        ldsm4(b0, smb + S2_A + bterm[0] + (cb ^ bxor[0]));
        ldsm4(b1, smb + S2_A + bterm[1] + (cb ^ bxor[1]));

        mma16816(acc[0][0], a0, b0[0], b0[2]);
        mma16816(acc[0][1], a0, b0[1], b0[3]);
        mma16816(acc[0][2], a0, b1[0], b1[2]);
        mma16816(acc[0][3], a0, b1[1], b1[3]);
        mma16816(acc[1][0], a1, b0[0], b0[2]);
        mma16816(acc[1][1], a1, b0[1], b0[3]);
        mma16816(acc[1][2], a1, b1[0], b1[2]);
        mma16816(acc[1][3], a1, b1[1], b1[3]);
    }
    __syncthreads();          // all ldsm reads complete; reuse smem for D

    // ---- stage scaled D into smem (stride-68 fp32 rows) ----
    const float sc = 1.0f / (float)RANK;
    float* ds = (float*)sm2;
    #pragma unroll
    for (int mt = 0; mt < 2; ++mt)
        #pragma unroll
        for (int nt = 0; nt < 4; ++nt) {
            int row = wm * 32 + mt * 16 + (lane >> 2);
            int col = wn * 32 + nt * 8 + 2 * (lane & 3);
            float2 v0 = { acc[mt][nt][0] * sc, acc[mt][nt][1] * sc };
            float2 v1 = { acc[mt][nt][2] * sc, acc[mt][nt][3] * sc };
            *(float2*)(ds + (size_t)row * S2_DS_STRIDE + col) = v0;
            *(float2*)(ds + (size_t)(row + 8) * S2_DS_STRIDE + col) = v1;
        }
    __syncthreads();

    // ---- coalesced write-out: STG.128, contiguous 64B per 16 lanes ----
    #pragma unroll
    for (int i = 0; i < 8; ++i) {
        int idx = tid + i * 256;             // 2048 float4 slots
        int row = idx >> 4, cg = idx & 15;
        float4 v = *(float4*)(ds + (size_t)row * S2_DS_STRIDE + cg * 4);
        *(float4*)(out + (size_t)(b * SEQ + m0 + row) * OUTF + o0 + cg * 4) = v;
    }
}

// ===========================================================================
extern "C" void kernel_launch(void* const* d_in, const int* in_sizes, int n_in,
                              void* d_out, int out_size)
{
    const float* x   = (const float*)d_in[0];
    const int*   ids = (const int*)  d_in[1];
    const float* A   = (const float*)d_in[2];
    const float* Bw  = (const float*)d_in[3];
    float* out = (float*)d_out;

    cudaFuncSetAttribute(lora_s1, cudaFuncAttributeMaxDynamicSharedMemorySize, S1_SMEM);
    cudaFuncSetAttribute(lora_s2, cudaFuncAttributeMaxDynamicSharedMemorySize, S2_SMEM);

    lora_prep_a<<<dim3(OUTF / 128, NADAPT), 256>>>(A);
    lora_s1<<<dim3(SEQ / 128, BATCH, KSPLIT), 256, S1_SMEM>>>(x, ids, Bw);
    lora_bx_reduce<<<BATCH * SEQ * RANK / 4 / 256, 256>>>();
    lora_s2<<<dim3(OUTF / 64, SEQ / 128, BATCH), 256, S2_SMEM>>>(ids, out);
}

// round 11
// speedup vs baseline: 1.5353x; 1.0759x over previous
#include <cuda_runtime.h>
#include <cuda_fp16.h>
#include <cstdint>

#define BATCH  4
#define SEQ    4096
#define HID    4096
#define OUTF   4096
#define RANK   64
#define NADAPT 8
#define KSPLIT 4

// ---------------------------------------------------------------------------
// Global scratch
// g_part: fp32 split-K partials [kp][b][s][r]
// g_bx:  fp16 [b][s][r]     g_at: fp16 [a][o][r]  (K-major, packed half2)
// ---------------------------------------------------------------------------
__device__ __align__(16) float    g_part[(size_t)KSPLIT * BATCH * SEQ * RANK];
__device__ __align__(16) uint32_t g_bx[BATCH * SEQ * RANK / 2];
__device__ __align__(16) uint32_t g_at[NADAPT * OUTF * RANK / 2];

#define SW128(b) ((b) ^ (((b) >> 3) & 0x70))

__device__ __forceinline__ uint32_t smem_u32(const void* p) {
    uint32_t a;
    asm("{ .reg .u64 t; cvta.to.shared.u64 t, %1; cvt.u32.u64 %0, t; }"
        : "=r"(a) : "l"(p));
    return a;
}

__device__ __forceinline__ void ldsm4(uint32_t r[4], uint32_t addr) {
    asm volatile("ldmatrix.sync.aligned.m8n8.x4.shared.b16 {%0,%1,%2,%3}, [%4];"
        : "=r"(r[0]), "=r"(r[1]), "=r"(r[2]), "=r"(r[3]) : "r"(addr));
}

__device__ __forceinline__ void mma16816(float c[4], const uint32_t a[4],
                                         uint32_t b0, uint32_t b1) {
    asm volatile(
        "mma.sync.aligned.m16n8k16.row.col.f32.f16.f16.f32 "
        "{%0,%1,%2,%3}, {%4,%5,%6,%7}, {%8,%9}, {%0,%1,%2,%3};"
        : "+f"(c[0]), "+f"(c[1]), "+f"(c[2]), "+f"(c[3])
        : "r"(a[0]), "r"(a[1]), "r"(a[2]), "r"(a[3]), "r"(b0), "r"(b1));
}

// pack two floats -> one f16x2 word (lo = a, hi = b)
__device__ __forceinline__ uint32_t packh2(float a, float b) {
    uint32_t r;
    asm("cvt.rn.f16x2.f32 %0, %1, %2;" : "=r"(r) : "f"(b), "f"(a));
    return r;
}

// streaming (evict-first) stores/loads for zero-reuse data
__device__ __forceinline__ void stg_cs_f2(float* p, float2 v) {
    asm volatile("st.global.cs.v2.f32 [%0], {%1, %2};"
                 :: "l"(p), "f"(v.x), "f"(v.y) : "memory");
}
__device__ __forceinline__ float4 ldg_cs_f4(const float4* p) {
    float4 v;
    asm volatile("ld.global.cs.v4.f32 {%0,%1,%2,%3}, [%4];"
                 : "=f"(v.x), "=f"(v.y), "=f"(v.z), "=f"(v.w) : "l"(p));
    return v;
}

#define CPASYNC16(sm, gp) \
    asm volatile("cp.async.cg.shared.global [%0], [%1], 16;" \
                 :: "r"(sm), "l"(gp) : "memory")
#define CPASYNC_COMMIT() asm volatile("cp.async.commit_group;" ::: "memory")
#define CPASYNC_WAIT0()  asm volatile("cp.async.wait_group 0;" ::: "memory")

// ===========================================================================
// prep_A: A[a][r][o] fp32 -> g_at [a][o][r] fp16 (K-major)
// grid (32 o-tiles, 8 adapters), 256 thr
// ===========================================================================
__global__ __launch_bounds__(256) void lora_prep_a(const float* __restrict__ A) {
    __shared__ float As[64][132];
    const int a  = blockIdx.y;
    const int o0 = blockIdx.x * 128;
    const int tid = threadIdx.x;

    #pragma unroll
    for (int i = 0; i < 8; ++i) {
        int idx = tid + i * 256;
        int r = idx >> 5, og = idx & 31;
        *(float4*)&As[r][og * 4] =
            *(const float4*)(A + (size_t)a * RANK * OUTF + (size_t)r * OUTF + o0 + og * 4);
    }
    __syncthreads();

    const int o = tid >> 1, r0 = (tid & 1) * 32;
    __align__(16) uint32_t hb[16];
    #pragma unroll
    for (int j = 0; j < 16; ++j)
        hb[j] = packh2(As[r0 + 2 * j][o], As[r0 + 2 * j + 1][o]);

    size_t base = ((size_t)(a * OUTF + o0 + o) * RANK + r0) / 2;   // uint32 units
    #pragma unroll
    for (int q = 0; q < 4; ++q)
        *(uint4*)(g_at + base + q * 4) = *(uint4*)(hb + q * 4);
}

// ===========================================================================
// Stage 1: partial[kp][b][s][r] = x[b][s][k0:k0+1024] @ B[k0:k0+1024][a][r]
// CTA 128M x 64N, split-K=4, 16 chunks of 64, ping-pong smem, 1 barrier/chunk.
// Single-pass fp16. 8 warps = 4M x 2N, warp tile 32x32. grid (32,4,4), 2/SM.
// (minblocks MUST stay 2: reg cap 128; minblocks 3 caps at 85 -> spills, R9.)
// ===========================================================================
#define S1_X   0
#define S1_B   16384
#define S1_BUF 24576
#define S1_SMEM (2 * S1_BUF)
#define S1_KC   (HID / KSPLIT / 64)     // 16 chunks

__global__ __launch_bounds__(256, 2) void lora_s1(
    const float* __restrict__ x, const int* __restrict__ ids,
    const float* __restrict__ Bw)
{
    extern __shared__ __align__(128) uint8_t sm1[];
    const int tid = threadIdx.x, lane = tid & 31, wid = tid >> 5;
    const int wm = wid & 3, wn = wid >> 2;           // 4M x 2N warps
    const int b = blockIdx.y;
    const int kp = blockIdx.z;
    const int a = ids[b];
    const int m0 = blockIdx.x * 128;
    const int k0 = kp * (HID / KSPLIT);

    const uint32_t smb = smem_u32(sm1);
    const int lr = lane & 15;
    const uint32_t lcol = (uint32_t)(lane >> 4) * 16;

    uint32_t aterm[2], axor[2], bterm[2], bxor[2];
    #pragma unroll
    for (int t = 0; t < 2; ++t) {
        int ar = wm * 32 + t * 16 + lr;
        aterm[t] = (uint32_t)ar * 128; axor[t] = (uint32_t)(ar & 7) << 4;
        int br = wn * 32 + t * 16 + lr;
        bterm[t] = (uint32_t)br * 128; bxor[t] = (uint32_t)(br & 7) << 4;
    }

    float acc[2][4][4];
    #pragma unroll
    for (int i = 0; i < 2; ++i)
        #pragma unroll
        for (int j = 0; j < 4; ++j)
            #pragma unroll
            for (int k = 0; k < 4; ++k) acc[i][j][k] = 0.f;

    // per-thread load/convert coordinates
    const int xkg = tid & 15;                 // k-group within 64 (4 k each)
    const int bih = tid & 31;                 // h-pair index (conflict-free STS)
    const int brg0 = tid >> 5;                // rank groups brg0 and brg0+8

    float4 xv[8], bv0[2], bv1[2];

    // ---- prefetch chunk 0 ----
    #pragma unroll
    for (int i = 0; i < 8; ++i) {
        int m = (tid + i * 256) >> 4;
        xv[i] = *(const float4*)(x + (size_t)(b * SEQ + m0 + m) * HID + k0 + xkg * 4);
    }
    #pragma unroll
    for (int i = 0; i < 2; ++i) {
        const float* p = Bw + (size_t)(k0 + 2 * bih) * (NADAPT * RANK) + a * RANK
                       + (brg0 + i * 8) * 4;
        bv0[i] = *(const float4*)p;
        bv1[i] = *(const float4*)(p + NADAPT * RANK);
    }

    // ---- convert chunk 0 into buf 0 ----
    #pragma unroll
    for (int i = 0; i < 8; ++i) {
        int m = (tid + i * 256) >> 4;
        uint32_t s0 = SW128((uint32_t)m * 128 + xkg * 8);
        *(uint2*)(sm1 + S1_X + s0) =
            make_uint2(packh2(xv[i].x, xv[i].y), packh2(xv[i].z, xv[i].w));
    }
    #pragma unroll
    for (int i = 0; i < 2; ++i) {
        const float* f0 = &bv0[i].x;
        const float* f1 = &bv1[i].x;
        #pragma unroll
        for (int j = 0; j < 4; ++j) {
            uint32_t so = SW128((uint32_t)((brg0 + i * 8) * 4 + j) * 128 + bih * 4);
            *(uint32_t*)(sm1 + S1_B + so) = packh2(f0[j], f1[j]);
        }
    }
    __syncthreads();

    for (int it = 0; it < S1_KC; ++it) {
        const uint32_t pb = (uint32_t)(it & 1) * S1_BUF;

        // ---- prefetch chunk it+1 (LDG latency hides under MMA) ----
        if (it + 1 < S1_KC) {
            int kc = k0 + (it + 1) * 64;
            #pragma unroll
            for (int i = 0; i < 8; ++i) {
                int m = (tid + i * 256) >> 4;
                xv[i] = *(const float4*)(x + (size_t)(b * SEQ + m0 + m) * HID + kc + xkg * 4);
            }
            #pragma unroll
            for (int i = 0; i < 2; ++i) {
                const float* p = Bw + (size_t)(kc + 2 * bih) * (NADAPT * RANK) + a * RANK
                               + (brg0 + i * 8) * 4;
                bv0[i] = *(const float4*)p;
                bv1[i] = *(const float4*)(p + NADAPT * RANK);
            }
        }

        // ---- MMA over buf pb ----
        #pragma unroll
        for (int ks = 0; ks < 4; ++ks) {
            uint32_t cb = lcol + (uint32_t)ks * 32;
            uint32_t a0[4], a1[4], b0[4], b1[4];
            ldsm4(a0, smb + S1_X + pb + aterm[0] + (cb ^ axor[0]));
            ldsm4(a1, smb + S1_X + pb + aterm[1] + (cb ^ axor[1]));
            ldsm4(b0, smb + S1_B + pb + bterm[0] + (cb ^ bxor[0]));
            ldsm4(b1, smb + S1_B + pb + bterm[1] + (cb ^ bxor[1]));

            mma16816(acc[0][0], a0, b0[0], b0[2]);
            mma16816(acc[0][1], a0, b0[1], b0[3]);
            mma16816(acc[0][2], a0, b1[0], b1[2]);
            mma16816(acc[0][3], a0, b1[1], b1[3]);
            mma16816(acc[1][0], a1, b0[0], b0[2]);
            mma16816(acc[1][1], a1, b0[1], b0[3]);
            mma16816(acc[1][2], a1, b1[0], b1[2]);
            mma16816(acc[1][3], a1, b1[1], b1[3]);
        }

        // ---- convert chunk it+1 into the other buffer ----
        if (it + 1 < S1_KC) {
            const uint32_t qb = pb ^ S1_BUF;
            #pragma unroll
            for (int i = 0; i < 8; ++i) {
                int m = (tid + i * 256) >> 4;
                uint32_t s0 = SW128((uint32_t)m * 128 + xkg * 8);
                *(uint2*)(sm1 + S1_X + qb + s0) =
                    make_uint2(packh2(xv[i].x, xv[i].y), packh2(xv[i].z, xv[i].w));
            }
            #pragma unroll
            for (int i = 0; i < 2; ++i) {
                const float* f0 = &bv0[i].x;
                const float* f1 = &bv1[i].x;
                #pragma unroll
                for (int j = 0; j < 4; ++j) {
                    uint32_t so = SW128((uint32_t)((brg0 + i * 8) * 4 + j) * 128 + bih * 4);
                    *(uint32_t*)(sm1 + S1_B + qb + so) = packh2(f0[j], f1[j]);
                }
            }
        }
        __syncthreads();
    }

    // ---- epilogue: raw fp32 partial sums (streaming stores, zero reuse soon) ----
    float* pp = g_part + (size_t)(kp * BATCH + b) * SEQ * RANK;
    #pragma unroll
    for (int mt = 0; mt < 2; ++mt)
        #pragma unroll
        for (int nt = 0; nt < 4; ++nt)
            #pragma unroll
            for (int rh = 0; rh < 2; ++rh) {
                int s = m0 + wm * 32 + mt * 16 + rh * 8 + (lane >> 2);
                int r = wn * 32 + nt * 8 + 2 * (lane & 3);
                float2 v = { acc[mt][nt][2 * rh], acc[mt][nt][2 * rh + 1] };
                stg_cs_f2(pp + (size_t)s * RANK + r, v);
            }
}

// ===========================================================================
// bx_reduce: sum 4 split-K partials -> fp16 g_bx
// grid 1024 x 256 thr, one float4 (4 elems) per thread. Streaming loads.
// ===========================================================================
__global__ __launch_bounds__(256) void lora_bx_reduce() {
    const size_t gid = (size_t)blockIdx.x * 256 + threadIdx.x;   // float4 units
    const size_t stride = (size_t)BATCH * SEQ * RANK / 4;
    const float4* p = (const float4*)g_part;
    float4 v0 = ldg_cs_f4(p + gid);
    float4 v1 = ldg_cs_f4(p + gid + stride);
    float4 v2 = ldg_cs_f4(p + gid + 2 * stride);
    float4 v3 = ldg_cs_f4(p + gid + 3 * stride);
    float4 s;
    s.x = (v0.x + v1.x) + (v2.x + v3.x);
    s.y = (v0.y + v1.y) + (v2.y + v3.y);
    s.z = (v0.z + v1.z) + (v2.z + v3.z);
    s.w = (v0.w + v1.w) + (v2.w + v3.w);
    ((uint2*)g_bx)[gid] = make_uint2(packh2(s.x, s.y), packh2(s.z, s.w));
}

// ===========================================================================
// Stage 2: out[b][s][o] = Bx[b][s][:] @ At[a][o][:] / 64
// CTA 128M x 64N, K=64 one-shot, fp16, cp.async fill. Direct float2 stores
// (R8-proven; smem staging regressed in R9/R10) with .cs streaming hint.
// 8 warps = 4M x 2N, warp tile 32x32. 24 KB smem. grid (64, 32, 4).
// ===========================================================================
#define S2_X 0
#define S2_A 16384
#define S2_SMEM 24576

__global__ __launch_bounds__(256, 3) void lora_s2(
    const int* __restrict__ ids, float* __restrict__ out)
{
    extern __shared__ __align__(128) uint8_t sm2[];
    const int tid = threadIdx.x, lane = tid & 31, wid = tid >> 5;
    const int wm = wid & 3, wn = wid >> 2;           // 4M x 2N warps
    const int o0 = blockIdx.x * 64, m0 = blockIdx.y * 128, b = blockIdx.z;
    const int a = ids[b];

    const uint32_t smb = smem_u32(sm2);

    // ---- cp.async smem fill (rows are 128B: 64 fp16 K-major) ----
    #pragma unroll
    for (int i = 0; i < 4; ++i) {
        int idx = tid + i * 256;             // 1024 uint4 slots
        int row = idx >> 3, rg = idx & 7;
        uint32_t so = SW128((uint32_t)row * 128 + rg * 16);
        size_t bx = (size_t)(b * SEQ + m0 + row) * 8 + rg;
        CPASYNC16(smb + S2_X + so, (const uint4*)g_bx + bx);
    }
    #pragma unroll
    for (int i = 0; i < 2; ++i) {
        int idx = tid + i * 256;             // 512 uint4 slots
        int row = idx >> 3, rg = idx & 7;
        uint32_t so = SW128((uint32_t)row * 128 + rg * 16);
        size_t at = (size_t)(a * OUTF + o0 + row) * 8 + rg;
        CPASYNC16(smb + S2_A + so, (const uint4*)g_at + at);
    }
    CPASYNC_COMMIT();
    CPASYNC_WAIT0();
    __syncthreads();

    const int lr = lane & 15;
    const uint32_t lcol = (uint32_t)(lane >> 4) * 16;

    uint32_t aterm[2], axor[2], bterm[2], bxor[2];
    #pragma unroll
    for (int t = 0; t < 2; ++t) {
        int ar = wm * 32 + t * 16 + lr;
        aterm[t] = (uint32_t)ar * 128; axor[t] = (uint32_t)(ar & 7) << 4;
        int br = wn * 32 + t * 16 + lr;
        bterm[t] = (uint32_t)br * 128; bxor[t] = (uint32_t)(br & 7) << 4;
    }

    float acc[2][4][4];
    #pragma unroll
    for (int i = 0; i < 2; ++i)
        #pragma unroll
        for (int j = 0; j < 4; ++j)
            #pragma unroll
            for (int k = 0; k < 4; ++k) acc[i][j][k] = 0.f;

    #pragma unroll
    for (int ks = 0; ks < 4; ++ks) {
        uint32_t cb = lcol + (uint32_t)ks * 32;
        uint32_t a0[4], a1[4], b0[4], b1[4];
        ldsm4(a0, smb + S2_X + aterm[0] + (cb ^ axor[0]));
        ldsm4(a1, smb + S2_X + aterm[1] + (cb ^ axor[1]));
        ldsm4(b0, smb + S2_A + bterm[0] + (cb ^ bxor[0]));
        ldsm4(b1, smb + S2_A + bterm[1] + (cb ^ bxor[1]));

        mma16816(acc[0][0], a0, b0[0], b0[2]);
        mma16816(acc[0][1], a0, b0[1], b0[3]);
        mma16816(acc[0][2], a0, b1[0], b1[2]);
        mma16816(acc[0][3], a0, b1[1], b1[3]);
        mma16816(acc[1][0], a1, b0[0], b0[2]);
        mma16816(acc[1][1], a1, b0[1], b0[3]);
        mma16816(acc[1][2], a1, b1[0], b1[2]);
        mma16816(acc[1][3], a1, b1[1], b1[3]);
    }

    // ---- epilogue: scaled direct streaming stores (R8 layout) ----
    const float sc = 1.0f / (float)RANK;
    #pragma unroll
    for (int mt = 0; mt < 2; ++mt)
        #pragma unroll
        for (int nt = 0; nt < 4; ++nt) {
            int row = m0 + wm * 32 + mt * 16 + (lane >> 2);
            int col = o0 + wn * 32 + nt * 8 + 2 * (lane & 3);
            float2 v0 = { acc[mt][nt][0] * sc, acc[mt][nt][1] * sc };
            float2 v1 = { acc[mt][nt][2] * sc, acc[mt][nt][3] * sc };
            stg_cs_f2(out + (size_t)(b * SEQ + row)     * OUTF + col, v0);
            stg_cs_f2(out + (size_t)(b * SEQ + row + 8) * OUTF + col, v1);
        }
}

// ===========================================================================
extern "C" void kernel_launch(void* const* d_in, const int* in_sizes, int n_in,
                              void* d_out, int out_size)
{
    const float* x   = (const float*)d_in[0];
    const int*   ids = (const int*)  d_in[1];
    const float* A   = (const float*)d_in[2];
    const float* Bw  = (const float*)d_in[3];
    float* out = (float*)d_out;

    cudaFuncSetAttribute(lora_s1, cudaFuncAttributeMaxDynamicSharedMemorySize, S1_SMEM);
    cudaFuncSetAttribute(lora_s2, cudaFuncAttributeMaxDynamicSharedMemorySize, S2_SMEM);

    lora_prep_a<<<dim3(OUTF / 128, NADAPT), 256>>>(A);
    lora_s1<<<dim3(SEQ / 128, BATCH, KSPLIT), 256, S1_SMEM>>>(x, ids, Bw);
    lora_bx_reduce<<<BATCH * SEQ * RANK / 4 / 256, 256>>>();
    lora_s2<<<dim3(OUTF / 64, SEQ / 128, BATCH), 256, S2_SMEM>>>(ids, out);
}

// round 12
// speedup vs baseline: 1.5756x; 1.0263x over previous
#include <cuda_runtime.h>
#include <cuda_fp16.h>
#include <cstdint>

#define BATCH  4
#define SEQ    4096
#define HID    4096
#define OUTF   4096
#define RANK   64
#define NADAPT 8
#define KSPLIT 4

// ---------------------------------------------------------------------------
// Global scratch
// g_part: fp32 split-K partials [kp][b][s][r]
// g_bx:  fp16 [b][s][r]     g_at: fp16 [a][o][r]  (K-major, packed half2)
// ---------------------------------------------------------------------------
__device__ __align__(16) float    g_part[(size_t)KSPLIT * BATCH * SEQ * RANK];
__device__ __align__(16) uint32_t g_bx[BATCH * SEQ * RANK / 2];
__device__ __align__(16) uint32_t g_at[NADAPT * OUTF * RANK / 2];

#define SW128(b) ((b) ^ (((b) >> 3) & 0x70))

__device__ __forceinline__ uint32_t smem_u32(const void* p) {
    uint32_t a;
    asm("{ .reg .u64 t; cvta.to.shared.u64 t, %1; cvt.u32.u64 %0, t; }"
        : "=r"(a) : "l"(p));
    return a;
}

__device__ __forceinline__ void ldsm4(uint32_t r[4], uint32_t addr) {
    asm volatile("ldmatrix.sync.aligned.m8n8.x4.shared.b16 {%0,%1,%2,%3}, [%4];"
        : "=r"(r[0]), "=r"(r[1]), "=r"(r[2]), "=r"(r[3]) : "r"(addr));
}

__device__ __forceinline__ void mma16816(float c[4], const uint32_t a[4],
                                         uint32_t b0, uint32_t b1) {
    asm volatile(
        "mma.sync.aligned.m16n8k16.row.col.f32.f16.f16.f32 "
        "{%0,%1,%2,%3}, {%4,%5,%6,%7}, {%8,%9}, {%0,%1,%2,%3};"
        : "+f"(c[0]), "+f"(c[1]), "+f"(c[2]), "+f"(c[3])
        : "r"(a[0]), "r"(a[1]), "r"(a[2]), "r"(a[3]), "r"(b0), "r"(b1));
}

// pack two floats -> one f16x2 word (lo = a, hi = b)
__device__ __forceinline__ uint32_t packh2(float a, float b) {
    uint32_t r;
    asm("cvt.rn.f16x2.f32 %0, %1, %2;" : "=r"(r) : "f"(b), "f"(a));
    return r;
}

// streaming (evict-first) stores/loads for zero-reuse data
__device__ __forceinline__ void stg_cs_f2(float* p, float2 v) {
    asm volatile("st.global.cs.v2.f32 [%0], {%1, %2};"
                 :: "l"(p), "f"(v.x), "f"(v.y) : "memory");
}
__device__ __forceinline__ float4 ldg_cs_f4(const float4* p) {
    float4 v;
    asm volatile("ld.global.cs.v4.f32 {%0,%1,%2,%3}, [%4];"
                 : "=f"(v.x), "=f"(v.y), "=f"(v.z), "=f"(v.w) : "l"(p));
    return v;
}

#define CPASYNC16(sm, gp) \
    asm volatile("cp.async.cg.shared.global [%0], [%1], 16;" \
                 :: "r"(sm), "l"(gp) : "memory")
#define CPASYNC_COMMIT() asm volatile("cp.async.commit_group;" ::: "memory")
#define CPASYNC_WAIT0()  asm volatile("cp.async.wait_group 0;" ::: "memory")

// ===========================================================================
// prep_A: A[a][r][o] fp32 -> g_at [a][o][r] fp16 (K-major)
// grid (32 o-tiles, 8 adapters), 256 thr
// ===========================================================================
__global__ __launch_bounds__(256) void lora_prep_a(const float* __restrict__ A) {
    __shared__ float As[64][132];
    const int a  = blockIdx.y;
    const int o0 = blockIdx.x * 128;
    const int tid = threadIdx.x;

    #pragma unroll
    for (int i = 0; i < 8; ++i) {
        int idx = tid + i * 256;
        int r = idx >> 5, og = idx & 31;
        *(float4*)&As[r][og * 4] =
            *(const float4*)(A + (size_t)a * RANK * OUTF + (size_t)r * OUTF + o0 + og * 4);
    }
    __syncthreads();

    const int o = tid >> 1, r0 = (tid & 1) * 32;
    __align__(16) uint32_t hb[16];
    #pragma unroll
    for (int j = 0; j < 16; ++j)
        hb[j] = packh2(As[r0 + 2 * j][o], As[r0 + 2 * j + 1][o]);

    size_t base = ((size_t)(a * OUTF + o0 + o) * RANK + r0) / 2;   // uint32 units
    #pragma unroll
    for (int q = 0; q < 4; ++q)
        *(uint4*)(g_at + base + q * 4) = *(uint4*)(hb + q * 4);
}

// ===========================================================================
// Stage 1: partial[kp][b][s][r] = x[b][s][k0:k0+1024] @ B[k0:k0+1024][a][r]
// CTA 128M x 64N, split-K=4, 16 chunks of 64, ping-pong smem, 1 barrier/chunk.
// Single-pass fp16. 8 warps = 4M x 2N, warp tile 32x32. grid (32,4,4), 2/SM.
// (minblocks MUST stay 2: reg cap 128; minblocks 3 caps at 85 -> spills, R9.)
// ===========================================================================
#define S1_X   0
#define S1_B   16384
#define S1_BUF 24576
#define S1_SMEM (2 * S1_BUF)
#define S1_KC   (HID / KSPLIT / 64)     // 16 chunks

__global__ __launch_bounds__(256, 2) void lora_s1(
    const float* __restrict__ x, const int* __restrict__ ids,
    const float* __restrict__ Bw)
{
    extern __shared__ __align__(128) uint8_t sm1[];
    const int tid = threadIdx.x, lane = tid & 31, wid = tid >> 5;
    const int wm = wid & 3, wn = wid >> 2;           // 4M x 2N warps
    const int b = blockIdx.y;
    const int kp = blockIdx.z;
    const int a = ids[b];
    const int m0 = blockIdx.x * 128;
    const int k0 = kp * (HID / KSPLIT);

    const uint32_t smb = smem_u32(sm1);
    const int lr = lane & 15;
    const uint32_t lcol = (uint32_t)(lane >> 4) * 16;

    uint32_t aterm[2], axor[2], bterm[2], bxor[2];
    #pragma unroll
    for (int t = 0; t < 2; ++t) {
        int ar = wm * 32 + t * 16 + lr;
        aterm[t] = (uint32_t)ar * 128; axor[t] = (uint32_t)(ar & 7) << 4;
        int br = wn * 32 + t * 16 + lr;
        bterm[t] = (uint32_t)br * 128; bxor[t] = (uint32_t)(br & 7) << 4;
    }

    float acc[2][4][4];
    #pragma unroll
    for (int i = 0; i < 2; ++i)
        #pragma unroll
        for (int j = 0; j < 4; ++j)
            #pragma unroll
            for (int k = 0; k < 4; ++k) acc[i][j][k] = 0.f;

    // per-thread load/convert coordinates
    const int xkg = tid & 15;                 // k-group within 64 (4 k each)
    const int bih = tid & 31;                 // h-pair index (conflict-free STS)
    const int brg0 = tid >> 5;                // rank groups brg0 and brg0+8

    float4 xv[8], bv0[2], bv1[2];

    // ---- prefetch chunk 0 ----
    #pragma unroll
    for (int i = 0; i < 8; ++i) {
        int m = (tid + i * 256) >> 4;
        xv[i] = *(const float4*)(x + (size_t)(b * SEQ + m0 + m) * HID + k0 + xkg * 4);
    }
    #pragma unroll
    for (int i = 0; i < 2; ++i) {
        const float* p = Bw + (size_t)(k0 + 2 * bih) * (NADAPT * RANK) + a * RANK
                       + (brg0 + i * 8) * 4;
        bv0[i] = *(const float4*)p;
        bv1[i] = *(const float4*)(p + NADAPT * RANK);
    }

    // ---- convert chunk 0 into buf 0 ----
    #pragma unroll
    for (int i = 0; i < 8; ++i) {
        int m = (tid + i * 256) >> 4;
        uint32_t s0 = SW128((uint32_t)m * 128 + xkg * 8);
        *(uint2*)(sm1 + S1_X + s0) =
            make_uint2(packh2(xv[i].x, xv[i].y), packh2(xv[i].z, xv[i].w));
    }
    #pragma unroll
    for (int i = 0; i < 2; ++i) {
        const float* f0 = &bv0[i].x;
        const float* f1 = &bv1[i].x;
        #pragma unroll
        for (int j = 0; j < 4; ++j) {
            uint32_t so = SW128((uint32_t)((brg0 + i * 8) * 4 + j) * 128 + bih * 4);
            *(uint32_t*)(sm1 + S1_B + so) = packh2(f0[j], f1[j]);
        }
    }
    __syncthreads();

    for (int it = 0; it < S1_KC; ++it) {
        const uint32_t pb = (uint32_t)(it & 1) * S1_BUF;

        // ---- prefetch chunk it+1 (LDG latency hides under MMA) ----
        if (it + 1 < S1_KC) {
            int kc = k0 + (it + 1) * 64;
            #pragma unroll
            for (int i = 0; i < 8; ++i) {
                int m = (tid + i * 256) >> 4;
                xv[i] = *(const float4*)(x + (size_t)(b * SEQ + m0 + m) * HID + kc + xkg * 4);
            }
            #pragma unroll
            for (int i = 0; i < 2; ++i) {
                const float* p = Bw + (size_t)(kc + 2 * bih) * (NADAPT * RANK) + a * RANK
                               + (brg0 + i * 8) * 4;
                bv0[i] = *(const float4*)p;
                bv1[i] = *(const float4*)(p + NADAPT * RANK);
            }
        }

        // ---- MMA over buf pb ----
        #pragma unroll
        for (int ks = 0; ks < 4; ++ks) {
            uint32_t cb = lcol + (uint32_t)ks * 32;
            uint32_t a0[4], a1[4], b0[4], b1[4];
            ldsm4(a0, smb + S1_X + pb + aterm[0] + (cb ^ axor[0]));
            ldsm4(a1, smb + S1_X + pb + aterm[1] + (cb ^ axor[1]));
            ldsm4(b0, smb + S1_B + pb + bterm[0] + (cb ^ bxor[0]));
            ldsm4(b1, smb + S1_B + pb + bterm[1] + (cb ^ bxor[1]));

            mma16816(acc[0][0], a0, b0[0], b0[2]);
            mma16816(acc[0][1], a0, b0[1], b0[3]);
            mma16816(acc[0][2], a0, b1[0], b1[2]);
            mma16816(acc[0][3], a0, b1[1], b1[3]);
            mma16816(acc[1][0], a1, b0[0], b0[2]);
            mma16816(acc[1][1], a1, b0[1], b0[3]);
            mma16816(acc[1][2], a1, b1[0], b1[2]);
            mma16816(acc[1][3], a1, b1[1], b1[3]);
        }

        // ---- convert chunk it+1 into the other buffer ----
        if (it + 1 < S1_KC) {
            const uint32_t qb = pb ^ S1_BUF;
            #pragma unroll
            for (int i = 0; i < 8; ++i) {
                int m = (tid + i * 256) >> 4;
                uint32_t s0 = SW128((uint32_t)m * 128 + xkg * 8);
                *(uint2*)(sm1 + S1_X + qb + s0) =
                    make_uint2(packh2(xv[i].x, xv[i].y), packh2(xv[i].z, xv[i].w));
            }
            #pragma unroll
            for (int i = 0; i < 2; ++i) {
                const float* f0 = &bv0[i].x;
                const float* f1 = &bv1[i].x;
                #pragma unroll
                for (int j = 0; j < 4; ++j) {
                    uint32_t so = SW128((uint32_t)((brg0 + i * 8) * 4 + j) * 128 + bih * 4);
                    *(uint32_t*)(sm1 + S1_B + qb + so) = packh2(f0[j], f1[j]);
                }
            }
        }
        __syncthreads();
    }

    // ---- epilogue: raw fp32 partial sums (streaming stores) ----
    float* pp = g_part + (size_t)(kp * BATCH + b) * SEQ * RANK;
    #pragma unroll
    for (int mt = 0; mt < 2; ++mt)
        #pragma unroll
        for (int nt = 0; nt < 4; ++nt)
            #pragma unroll
            for (int rh = 0; rh < 2; ++rh) {
                int s = m0 + wm * 32 + mt * 16 + rh * 8 + (lane >> 2);
                int r = wn * 32 + nt * 8 + 2 * (lane & 3);
                float2 v = { acc[mt][nt][2 * rh], acc[mt][nt][2 * rh + 1] };
                stg_cs_f2(pp + (size_t)s * RANK + r, v);
            }
}

// ===========================================================================
// bx_reduce: sum 4 split-K partials -> fp16 g_bx
// grid 1024 x 256 thr, one float4 (4 elems) per thread. Streaming loads.
// ===========================================================================
__global__ __launch_bounds__(256) void lora_bx_reduce() {
    const size_t gid = (size_t)blockIdx.x * 256 + threadIdx.x;   // float4 units
    const size_t stride = (size_t)BATCH * SEQ * RANK / 4;
    const float4* p = (const float4*)g_part;
    float4 v0 = ldg_cs_f4(p + gid);
    float4 v1 = ldg_cs_f4(p + gid + stride);
    float4 v2 = ldg_cs_f4(p + gid + 2 * stride);
    float4 v3 = ldg_cs_f4(p + gid + 3 * stride);
    float4 s;
    s.x = (v0.x + v1.x) + (v2.x + v3.x);
    s.y = (v0.y + v1.y) + (v2.y + v3.y);
    s.z = (v0.z + v1.z) + (v2.z + v3.z);
    s.w = (v0.w + v1.w) + (v2.w + v3.w);
    ((uint2*)g_bx)[gid] = make_uint2(packh2(s.x, s.y), packh2(s.z, s.w));
}

// ===========================================================================
// Stage 2: out[b][s][o] = Bx[b][s][:] @ At[a][o][:] / 64
// CTA 128M x 128N, K=64 one-shot, fp16, cp.async fill, 512 thr = 16 warps
// (4M x 4N, warp tile 32x32). Direct .cs float2 stores (R8-proven layout).
// 32 KB smem. grid (32, 32, 4) = 4096 CTAs; halves operand refetch traffic.
// ===========================================================================
#define S2_X 0
#define S2_A 16384
#define S2_SMEM 32768

__global__ __launch_bounds__(512, 2) void lora_s2(
    const int* __restrict__ ids, float* __restrict__ out)
{
    extern __shared__ __align__(128) uint8_t sm2[];
    const int tid = threadIdx.x, lane = tid & 31, wid = tid >> 5;
    const int wm = wid & 3, wn = wid >> 2;           // 4M x 4N warps
    const int o0 = blockIdx.x * 128, m0 = blockIdx.y * 128, b = blockIdx.z;
    const int a = ids[b];

    const uint32_t smb = smem_u32(sm2);

    // ---- cp.async smem fill (rows are 128B: 64 fp16 K-major) ----
    #pragma unroll
    for (int i = 0; i < 2; ++i) {
        int idx = tid + i * 512;             // 1024 uint4 slots per tile
        int row = idx >> 3, rg = idx & 7;
        uint32_t so = SW128((uint32_t)row * 128 + rg * 16);
        size_t bx = (size_t)(b * SEQ + m0 + row) * 8 + rg;
        size_t at = (size_t)(a * OUTF + o0 + row) * 8 + rg;
        CPASYNC16(smb + S2_X + so, (const uint4*)g_bx + bx);
        CPASYNC16(smb + S2_A + so, (const uint4*)g_at + at);
    }
    CPASYNC_COMMIT();
    CPASYNC_WAIT0();
    __syncthreads();

    const int lr = lane & 15;
    const uint32_t lcol = (uint32_t)(lane >> 4) * 16;

    uint32_t aterm[2], axor[2], bterm[2], bxor[2];
    #pragma unroll
    for (int t = 0; t < 2; ++t) {
        int ar = wm * 32 + t * 16 + lr;
        aterm[t] = (uint32_t)ar * 128; axor[t] = (uint32_t)(ar & 7) << 4;
        int br = wn * 32 + t * 16 + lr;
        bterm[t] = (uint32_t)br * 128; bxor[t] = (uint32_t)(br & 7) << 4;
    }

    float acc[2][4][4];
    #pragma unroll
    for (int i = 0; i < 2; ++i)
        #pragma unroll
        for (int j = 0; j < 4; ++j)
            #pragma unroll
            for (int k = 0; k < 4; ++k) acc[i][j][k] = 0.f;

    #pragma unroll
    for (int ks = 0; ks < 4; ++ks) {
        uint32_t cb = lcol + (uint32_t)ks * 32;
        uint32_t a0[4], a1[4], b0[4], b1[4];
        ldsm4(a0, smb + S2_X + aterm[0] + (cb ^ axor[0]));
        ldsm4(a1, smb + S2_X + aterm[1] + (cb ^ axor[1]));
        ldsm4(b0, smb + S2_A + bterm[0] + (cb ^ bxor[0]));
        ldsm4(b1, smb + S2_A + bterm[1] + (cb ^ bxor[1]));

        mma16816(acc[0][0], a0, b0[0], b0[2]);
        mma16816(acc[0][1], a0, b0[1], b0[3]);
        mma16816(acc[0][2], a0, b1[0], b1[2]);
        mma16816(acc[0][3], a0, b1[1], b1[3]);
        mma16816(acc[1][0], a1, b0[0], b0[2]);
        mma16816(acc[1][1], a1, b0[1], b0[3]);
        mma16816(acc[1][2], a1, b1[0], b1[2]);
        mma16816(acc[1][3], a1, b1[1], b1[3]);
    }

    // ---- epilogue: scaled direct streaming stores ----
    const float sc = 1.0f / (float)RANK;
    #pragma unroll
    for (int mt = 0; mt < 2; ++mt)
        #pragma unroll
        for (int nt = 0; nt < 4; ++nt) {
            int row = m0 + wm * 32 + mt * 16 + (lane >> 2);
            int col = o0 + wn * 32 + nt * 8 + 2 * (lane & 3);
            float2 v0 = { acc[mt][nt][0] * sc, acc[mt][nt][1] * sc };
            float2 v1 = { acc[mt][nt][2] * sc, acc[mt][nt][3] * sc };
            stg_cs_f2(out + (size_t)(b * SEQ + row)     * OUTF + col, v0);
            stg_cs_f2(out + (size_t)(b * SEQ + row + 8) * OUTF + col, v1);
        }
}

// ===========================================================================
extern "C" void kernel_launch(void* const* d_in, const int* in_sizes, int n_in,
                              void* d_out, int out_size)
{
    const float* x   = (const float*)d_in[0];
    const int*   ids = (const int*)  d_in[1];
    const float* A   = (const float*)d_in[2];
    const float* Bw  = (const float*)d_in[3];
    float* out = (float*)d_out;

    cudaFuncSetAttribute(lora_s1, cudaFuncAttributeMaxDynamicSharedMemorySize, S1_SMEM);
    cudaFuncSetAttribute(lora_s2, cudaFuncAttributeMaxDynamicSharedMemorySize, S2_SMEM);

    lora_prep_a<<<dim3(OUTF / 128, NADAPT), 256>>>(A);
    lora_s1<<<dim3(SEQ / 128, BATCH, KSPLIT), 256, S1_SMEM>>>(x, ids, Bw);
    lora_bx_reduce<<<BATCH * SEQ * RANK / 4 / 256, 256>>>();
    lora_s2<<<dim3(OUTF / 128, SEQ / 128, BATCH), 512, S2_SMEM>>>(ids, out);
}